// round 15
// baseline (speedup 1.0000x reference)
#include <cuda_runtime.h>
#include <cuda_bf16.h>
#include <stdint.h>
#include <math.h>

#define Dc 256
#define Kc 64
#define TN 64
#define NTHREADS 256

#if defined(__CUDA_ARCH_FEAT_SM103_ALL) || defined(__CUDA_ARCH_FEAT_SM100_ALL)
#define TC_OK 1
#else
#define TC_OK 0
#endif

// ---- shared memory layout (bytes, from dynamic smem base) ----
#define SM_TMEMPTR 0
#define SM_MB1A    16          // mb1[0]@+16, mb1[1]@+24
#define SM_MB2A    32          // mb2[0]@+32, mb2[1]@+40
#define SM_B       64          // 64 floats bias (pre-scaled by log2e)
#define SM_SCRP    512         // 128 floats partial sums
#define SM_WH      2048        // W hi [128 k2][256 d] bf16 SW128 blocked (64KB)
#define SM_XDH0    (SM_WH   + 65536)   // X hi buf0 [256 d][64 n] (32KB)
#define SM_XDH1    (SM_XDH0 + 32768)
#define SM_AH0     (SM_XDH1 + 32768)   // a hi buf0 [64 k][64 n] (8KB)
#define SM_AH1     (SM_AH0  + 8192)
#define SM_TOTAL   (SM_AH1  + 8192)    // 149504 B

// idesc: kind::f16, dtype=F32, atype=btype=BF16, N=64, M=128
#define IDESC  ((1u<<4) | (1u<<7) | (1u<<10) | (8u<<17) | (8u<<24))
#define IDESC1 (IDESC | (1u<<16))       // + b_major (B is MN-major)

#define SWZ(o) ((o) ^ (((o) >> 3) & 0x70))

// SW128 descriptor: layout=2, version=1, SBO=64, LBO=1 (same for K/MN major;
// the b_major idesc bit carries the transpose).
#define DESC_BASE    0x4000404000010000ULL

#define LOG2E 1.4426950408889634f

__device__ float g_V[Kc * Dc];
__device__ float g_asum[Kc];
__device__ float g_Vn[Kc * Dc];   // column-normalized V (finalize scratch)
__device__ float g_rowp[4 * Kc];  // per-CTA row sumsq partials

// ------------------------- PTX helpers -------------------------
__device__ __forceinline__ uint32_t smem_u32(const void* p) {
    uint32_t a;
    asm("{ .reg .u64 t; cvta.to.shared.u64 t, %1; cvt.u32.u64 %0, t; }" : "=r"(a) : "l"(p));
    return a;
}
__device__ __forceinline__ uint64_t make_desc(uint32_t addr) {
    return DESC_BASE | ((uint64_t)(addr >> 4) & 0x3FFF);
}
#if TC_OK
__device__ __forceinline__ void mma_f16_ss(uint32_t d_tmem, uint64_t a_desc,
                                           uint64_t b_desc, uint32_t idesc, int acc) {
    asm volatile(
        "{\n\t.reg .pred p;\n\tsetp.ne.u32 p, %4, 0;\n\t"
        "tcgen05.mma.cta_group::1.kind::f16 [%0], %1, %2, %3, {%5, %5, %5, %5}, p;\n\t}"
        :: "r"(d_tmem), "l"(a_desc), "l"(b_desc), "r"(idesc), "r"((uint32_t)acc), "r"(0u)
        : "memory");
}
#endif
#define TC_COMMIT(mbar) \
    asm volatile("tcgen05.commit.cta_group::1.mbarrier::arrive::one.shared::cluster.b64 [%0];" \
                 :: "r"(mbar) : "memory")
#define TC_ALLOC(dst, n) \
    asm volatile("tcgen05.alloc.cta_group::1.sync.aligned.shared::cta.b32 [%0], %1;" \
                 :: "r"(dst), "r"(n) : "memory")
#define TC_RELINQ() asm volatile("tcgen05.relinquish_alloc_permit.cta_group::1.sync.aligned;")
#define TC_DEALLOC(base, n) \
    asm volatile("tcgen05.dealloc.cta_group::1.sync.aligned.b32 %0, %1;" :: "r"(base), "r"(n))
#define TC_WAIT_LD() asm volatile("tcgen05.wait::ld.sync.aligned;" ::: "memory")
#define TC_FENCE_AFTER() asm volatile("tcgen05.fence::after_thread_sync;" ::: "memory")
#define TC_FENCE_BEFORE() asm volatile("tcgen05.fence::before_thread_sync;" ::: "memory")
#define FENCE_ASYNC() asm volatile("fence.proxy.async.shared::cta;" ::: "memory")
#define MB_INIT(addr, cnt) \
    asm volatile("mbarrier.init.shared.b64 [%0], %1;" :: "r"(addr), "r"((uint32_t)(cnt)) : "memory")
#define MB_INVAL(addr) asm volatile("mbarrier.inval.shared.b64 [%0];" :: "r"(addr) : "memory")
#define BAR_SYNC(id, cnt) \
    asm volatile("bar.sync %0, %1;" :: "r"(id), "r"(cnt) : "memory")

#define MB_WAIT(mbar, ph) do {                                                  \
    uint32_t _m = (mbar); uint32_t _p = (uint32_t)(ph); uint32_t _done;         \
    asm volatile("{\n\t.reg .pred p;\n\t"                                       \
        "mbarrier.try_wait.parity.acquire.cta.shared::cta.b64 p, [%1], %2;\n\t" \
        "selp.b32 %0, 1, 0, p;\n\t}" : "=r"(_done) : "r"(_m), "r"(_p) : "memory"); \
    if (!_done) {                                                               \
        asm volatile("{\n\t.reg .pred P1;\n\t"                                  \
            "WL_%=:\n\t"                                                        \
            "mbarrier.try_wait.parity.acquire.cta.shared::cta.b64 P1, [%0], %1, 0x989680;\n\t" \
            "@P1 bra.uni WD_%=;\n\t"                                            \
            "bra.uni WL_%=;\n\t"                                                \
            "WD_%=:\n\t}" :: "r"(_m), "r"(_p) : "memory");                      \
    }                                                                           \
} while (0)

#define TC_LD_X32(r, addr)                                                      \
    asm volatile("tcgen05.ld.sync.aligned.32x32b.x32.b32 "                      \
        "{%0, %1, %2, %3, %4, %5, %6, %7, %8, %9, %10, %11, %12, %13, %14, %15, " \
        " %16, %17, %18, %19, %20, %21, %22, %23, %24, %25, %26, %27, %28, %29, %30, %31}, [%32];" \
        : "=r"((r)[0]),  "=r"((r)[1]),  "=r"((r)[2]),  "=r"((r)[3]),            \
          "=r"((r)[4]),  "=r"((r)[5]),  "=r"((r)[6]),  "=r"((r)[7]),            \
          "=r"((r)[8]),  "=r"((r)[9]),  "=r"((r)[10]), "=r"((r)[11]),           \
          "=r"((r)[12]), "=r"((r)[13]), "=r"((r)[14]), "=r"((r)[15]),           \
          "=r"((r)[16]), "=r"((r)[17]), "=r"((r)[18]), "=r"((r)[19]),           \
          "=r"((r)[20]), "=r"((r)[21]), "=r"((r)[22]), "=r"((r)[23]),           \
          "=r"((r)[24]), "=r"((r)[25]), "=r"((r)[26]), "=r"((r)[27]),           \
          "=r"((r)[28]), "=r"((r)[29]), "=r"((r)[30]), "=r"((r)[31])            \
        : "r"(addr))

__device__ __forceinline__ uint32_t b2u(__nv_bfloat162 v) {
    return *(uint32_t*)&v;
}

// ------------------------- main kernel -------------------------
__global__ __launch_bounds__(NTHREADS, 1) __cluster_dims__(1, 1, 1)
void netvlad_tc_kernel(const float* __restrict__ x,
                       const float* __restrict__ conv_w,
                       const float* __restrict__ conv_b,
                       int N, int numTiles) {
#if TC_OK
    extern __shared__ char smem[];
    const uint32_t sbase = smem_u32(smem);
    const int tid  = threadIdx.x;
    const int wid  = tid >> 5;
    const int lane = tid & 31;

    // init
    if (tid == 0) {
        MB_INIT(sbase + SM_MB1A + 0, 1); MB_INIT(sbase + SM_MB1A + 8, 1);
        MB_INIT(sbase + SM_MB2A + 0, 1); MB_INIT(sbase + SM_MB2A + 8, 1);
    }
    if (wid == 0) { TC_ALLOC(sbase + SM_TMEMPTR, 256); TC_RELINQ(); }
    if (tid < Kc) *(float*)(smem + SM_B + tid * 4) = conv_b[tid] * LOG2E;
    __syncthreads();
    uint32_t tmem;
    asm volatile("ld.shared.b32 %0, [%1];" : "=r"(tmem) : "r"(sbase + SM_TMEMPTR));

    // stage W hi (pre-scaled by log2e), M=128 (rows 64-127 duplicate rows 0-63).
    for (int i = tid; i < (Kc * Dc) / 4; i += NTHREADS) {
        int k = i >> 6;
        int d0 = (i & 63) * 4;
        float4 w4 = reinterpret_cast<const float4*>(conv_w)[i];
        __nv_bfloat162 h0 = __float22bfloat162_rn(make_float2(w4.x * LOG2E, w4.y * LOG2E));
        __nv_bfloat162 h1 = __float22bfloat162_rn(make_float2(w4.z * LOG2E, w4.w * LOG2E));
        uint32_t o = ((uint32_t)((k >> 3) + ((d0 >> 6) << 4)) << 10) + ((k & 7) << 7) + ((d0 & 63) << 1);
        o = SWZ(o);
        uint2 hv = make_uint2(b2u(h0), b2u(h1));
        *(uint2*)(smem + SM_WH + o) = hv;
        *(uint2*)(smem + SM_WH + o + 8192) = hv;
    }
    FENCE_ASYNC();
    __syncthreads();

    // descriptors
    const uint64_t dWh = make_desc(sbase + SM_WH);
    const uint64_t dX0 = make_desc(sbase + SM_XDH0);
    const uint64_t dX1 = make_desc(sbase + SM_XDH1);
    const uint64_t dA0 = make_desc(sbase + SM_AH0);
    const uint64_t dA1 = make_desc(sbase + SM_AH1);
    const float* sBf = (const float*)(smem + SM_B);
    float* scrP = (float*)(smem + SM_SCRP);

    float asum_local = 0.0f;
    int cnt = 0;
    int kk = 0;

    if (tid < 128) {
        // ================= PRODUCER (warps 0-3) =================
        uint32_t ph2 = 0;
        for (int tile = blockIdx.x; tile < numTiles; tile += gridDim.x, cnt++) {
            const int buf = cnt & 1;
            const int n0 = tile * TN;
            const int xb = buf ? SM_XDH1 : SM_XDH0;

            // all 32 LDG.128 issued before the wait (max MLP)
            float4 v[16], v2[16];
#pragma unroll
            for (int j = 0; j < 16; j++) {
                int i = tid + 128 * j;
                v[j] = *(reinterpret_cast<const float4*>(x + (size_t)(i >> 4) * N + n0) + (i & 15));
            }
#pragma unroll
            for (int j = 0; j < 16; j++) {
                int i = tid + 128 * (16 + j);
                v2[j] = *(reinterpret_cast<const float4*>(x + (size_t)(i >> 4) * N + n0) + (i & 15));
            }

            if (cnt >= 2) {
                MB_WAIT(sbase + SM_MB2A + 8 * buf, (ph2 >> buf) & 1);
                ph2 ^= (1u << buf);
            }

#pragma unroll
            for (int j = 0; j < 16; j++) {
                int i = tid + 128 * j;
                int d = i >> 4, n = (i & 15) * 4;
                __nv_bfloat162 h0 = __float22bfloat162_rn(make_float2(v[j].x, v[j].y));
                __nv_bfloat162 h1 = __float22bfloat162_rn(make_float2(v[j].z, v[j].w));
                uint32_t od = ((uint32_t)(d >> 3) << 10) + ((d & 7) << 7) + (n << 1);
                od = SWZ(od);
                *(uint2*)(smem + xb + od) = make_uint2(b2u(h0), b2u(h1));
            }
#pragma unroll
            for (int j = 0; j < 16; j++) {
                int i = tid + 128 * (16 + j);
                int d = i >> 4, n = (i & 15) * 4;
                __nv_bfloat162 h0 = __float22bfloat162_rn(make_float2(v2[j].x, v2[j].y));
                __nv_bfloat162 h1 = __float22bfloat162_rn(make_float2(v2[j].z, v2[j].w));
                uint32_t od = ((uint32_t)(d >> 3) << 10) + ((d & 7) << 7) + (n << 1);
                od = SWZ(od);
                *(uint2*)(smem + xb + od) = make_uint2(b2u(h0), b2u(h1));
            }
            FENCE_ASYNC();
            BAR_SYNC(1, 128);

            if (tid == 0) {
                const uint64_t bt = buf ? dX1 : dX0;
#pragma unroll
                for (int s = 0; s < 16; s++) {
                    uint64_t ao = (uint64_t)(((s >> 2) * 1024) + ((s & 3) * 2));
                    uint64_t bo = (uint64_t)(s * 128);
                    mma_f16_ss(tmem + buf * 64, dWh + ao, bt + bo, IDESC1, s != 0);
                }
                TC_COMMIT(sbase + SM_MB1A + 8 * buf);
            }
        }
    } else {
        // ================= CONSUMER (warps 4-7) =================
        const int cw = wid - 4;                 // 0..3
        kk = ((cw & 1) << 5) + lane;            // k index
        const int nh = cw >> 1;                 // n-half
        const float bk = sBf[kk];
        uint32_t ph1 = 0;

        for (int tile = blockIdx.x; tile < numTiles; tile += gridDim.x, cnt++) {
            const int buf = cnt & 1;
            const int ab = buf ? SM_AH1 : SM_AH0;

            MB_WAIT(sbase + SM_MB1A + 8 * buf, (ph1 >> buf) & 1);
            ph1 ^= (1u << buf);
            TC_FENCE_AFTER();
            uint32_t au[32];
            TC_LD_X32(au, tmem + buf * 64 + nh * 32);
            TC_WAIT_LD();
            TC_FENCE_BEFORE();

            float er[32], sr[32];
#pragma unroll
            for (int j = 0; j < 32; j++) {
                er[j] = exp2f(__uint_as_float(au[j]) + bk);
                sr[j] = er[j];
            }
            // fold-reduce: lane l ends with sum over 32 k-lanes for n = nh*32+l
#pragma unroll
            for (int off = 16; off > 0; off >>= 1) {
#pragma unroll
                for (int j = 0; j < 16; j++) {
                    if (j < off) {
                        float x0 = sr[j], x1 = sr[off + j];
                        float mine = (lane & off) ? x1 : x0;
                        float send = (lane & off) ? x0 : x1;
                        float theirs = __shfl_xor_sync(0xffffffffu, send, off);
                        sr[j] = mine + theirs;
                    }
                }
            }
            scrP[cw * 32 + lane] = sr[0];
            BAR_SYNC(2, 128);
            // lane l holds rinv for column n = nh*32 + l
            const float rinv_l = 1.0f / (sr[0] + scrP[(cw ^ 1) * 32 + lane]);

            float as = 0.0f;
#pragma unroll
            for (int q = 0; q < 4; q++) {
                uint32_t hv[4];
#pragma unroll
                for (int r = 0; r < 4; r++) {
                    int j = q * 8 + r * 2;
                    float a0 = er[j] * __shfl_sync(0xffffffffu, rinv_l, j);
                    float a1 = er[j + 1] * __shfl_sync(0xffffffffu, rinv_l, j + 1);
                    __nv_bfloat162 h2 = __float22bfloat162_rn(make_float2(a0, a1));
                    float2 f2 = __bfloat1622float2(h2);
                    as += f2.x + f2.y;   // asum from ROUNDED a (matches GEMM2 operand)
                    hv[r] = b2u(h2);
                }
                uint32_t o = ((uint32_t)(kk >> 3) << 10) + ((kk & 7) << 7) + ((uint32_t)(nh * 32 + q * 8) << 1);
                o = SWZ(o);
                *(uint4*)(smem + ab + o) = make_uint4(hv[0], hv[1], hv[2], hv[3]);
            }
            asum_local += as;
            FENCE_ASYNC();
            BAR_SYNC(2, 128);

            if (tid == 128) {
                const uint64_t dXp = buf ? dX1 : dX0;
                const uint64_t dAp = buf ? dA1 : dA0;
#pragma unroll
                for (int h = 0; h < 2; h++)
#pragma unroll
                    for (int s = 0; s < 4; s++) {
                        int acc = !(cnt == 0 && s == 0);
                        mma_f16_ss(tmem + 128 + 64 * h,
                                   dXp + (uint64_t)(h * 1024 + s * 2),
                                   dAp + (uint64_t)(s * 2), IDESC, acc);
                    }
                TC_COMMIT(sbase + SM_MB2A + 8 * buf);
            }
        }
    }

    __syncthreads();

    // ---- final: wait outstanding GEMM2 per buffer, then flush ----
    if (cnt >= 1) {
        int C0 = (cnt + 1) >> 1;
        int C1 = cnt >> 1;
        if (C0 >= 1) MB_WAIT(sbase + SM_MB2A + 0, (uint32_t)((C0 - 1) & 1));
        if (C1 >= 1) MB_WAIT(sbase + SM_MB2A + 8, (uint32_t)((C1 - 1) & 1));
        TC_FENCE_AFTER();
        uint32_t r[64];
        uint32_t cbase = tmem + 128 + ((tid >= 128) ? 64 : 0);
        TC_LD_X32(r, cbase);
        TC_LD_X32(r + 32, cbase + 32);
        TC_WAIT_LD();
#pragma unroll
        for (int c = 0; c < 64; c++)
            atomicAdd(&g_V[c * Dc + tid], __uint_as_float(r[c]));
        if (tid >= 128) atomicAdd(&g_asum[kk], asum_local);
    }
    __syncthreads();
    if (tid == 0) {
        MB_INVAL(sbase + SM_MB1A + 0); MB_INVAL(sbase + SM_MB1A + 8);
        MB_INVAL(sbase + SM_MB2A + 0); MB_INVAL(sbase + SM_MB2A + 8);
    }
    __syncthreads();
    if (wid == 0) TC_DEALLOC(tmem, 256);
#else
    // ---------- FFMA fallback (correct on non-a targets; never the fast path) ----------
    extern __shared__ float fsm[];
    float* sW  = fsm;                  // [64][257]
    float* sXT = sW + Kc * 257;        // [64][257]
    float* sA  = sXT + TN * 257;       // [64][65]
    float* sB  = sA + Kc * 65;         // [64]
    const int tid = threadIdx.x;
    for (int i = tid; i < (Kc * Dc) / 4; i += NTHREADS) {
        int k = (i * 4) / Dc, d = (i * 4) % Dc;
        float4 w4 = reinterpret_cast<const float4*>(conv_w)[i];
        float* p = &sW[k * 257 + d];
        p[0] = w4.x; p[1] = w4.y; p[2] = w4.z; p[3] = w4.w;
    }
    if (tid < Kc) sB[tid] = conv_b[tid];
    const int tn = tid & 15, tk = tid >> 4;
    const int td = tid & 31, tk2 = tid >> 5;
    float vacc[8][8];
#pragma unroll
    for (int i = 0; i < 8; i++)
#pragma unroll
        for (int j = 0; j < 8; j++) vacc[i][j] = 0.0f;
    float asum_acc = 0.0f;
    for (int tile = blockIdx.x; tile < numTiles; tile += gridDim.x) {
        const int n0 = tile * TN;
        __syncthreads();
        for (int i = tid; i < (Dc * TN) / 4; i += NTHREADS) {
            int d = i >> 4, ng = i & 15;
            float4 v = reinterpret_cast<const float4*>(x + (size_t)d * N + n0)[ng];
            int nb = ng * 4;
            sXT[(nb + 0) * 257 + d] = v.x; sXT[(nb + 1) * 257 + d] = v.y;
            sXT[(nb + 2) * 257 + d] = v.z; sXT[(nb + 3) * 257 + d] = v.w;
        }
        __syncthreads();
        float acc[4][4];
#pragma unroll
        for (int i = 0; i < 4; i++)
#pragma unroll
            for (int j = 0; j < 4; j++) acc[i][j] = 0.0f;
#pragma unroll 4
        for (int d = 0; d < Dc; d++) {
            float wv[4], xv[4];
#pragma unroll
            for (int i = 0; i < 4; i++) wv[i] = sW[(tk * 4 + i) * 257 + d];
#pragma unroll
            for (int j = 0; j < 4; j++) xv[j] = sXT[(tn * 4 + j) * 257 + d];
#pragma unroll
            for (int i = 0; i < 4; i++)
#pragma unroll
                for (int j = 0; j < 4; j++) acc[i][j] += wv[i] * xv[j];
        }
#pragma unroll
        for (int i = 0; i < 4; i++) {
            float b = sB[tk * 4 + i];
#pragma unroll
            for (int j = 0; j < 4; j++)
                sA[(tk * 4 + i) * 65 + (tn * 4 + j)] = acc[i][j] + b;
        }
        __syncthreads();
        if (tid < TN) {
            const int n = tid;
            float m = -1e30f;
            for (int k = 0; k < Kc; k++) m = fmaxf(m, sA[k * 65 + n]);
            float s = 0.0f;
            for (int k = 0; k < Kc; k++) {
                float e = __expf(sA[k * 65 + n] - m);
                sA[k * 65 + n] = e; s += e;
            }
            float r = 1.0f / s;
            for (int k = 0; k < Kc; k++) sA[k * 65 + n] *= r;
        }
        __syncthreads();
        if (tid < Kc) {
            float s = 0.0f;
            for (int n = 0; n < TN; n++) s += sA[tid * 65 + n];
            asum_acc += s;
        }
#pragma unroll 2
        for (int n = 0; n < TN; n++) {
            float av[8], xv[8];
#pragma unroll
            for (int i = 0; i < 8; i++) av[i] = sA[(tk2 * 8 + i) * 65 + n];
#pragma unroll
            for (int j = 0; j < 8; j++) xv[j] = sXT[n * 257 + td + 32 * j];
#pragma unroll
            for (int i = 0; i < 8; i++)
#pragma unroll
                for (int j = 0; j < 8; j++) vacc[i][j] += av[i] * xv[j];
        }
    }
#pragma unroll
    for (int i = 0; i < 8; i++)
#pragma unroll
        for (int j = 0; j < 8; j++)
            atomicAdd(&g_V[(tk2 * 8 + i) * Dc + td + 32 * j], vacc[i][j]);
    if (tid < Kc) atomicAdd(&g_asum[tid], asum_acc);
#endif
}

// ------------------------- finalize, stage 1 (4 CTAs x 256) -------------------------
// CTA b owns d-slice [b*64, b*64+64). Computes V = g_V - c*asum, column (axis-0)
// L2 over k (fully local), writes column-normalized slice to g_Vn and per-CTA
// row sumsq partials to g_rowp. Re-zeroes its g_V slice.
__global__ __launch_bounds__(256) void finalize1_kernel(const float* __restrict__ c) {
    __shared__ float sAs[64];
    __shared__ float sV[64 * 72];     // [k][dd], stride 72 (16B-aligned rows, conflict-free cols)
    __shared__ float sRinv[64];
    __shared__ float scr[256];

    const int tid = threadIdx.x;
    const int b = blockIdx.x;
    const int k = tid >> 2;                 // 0..63
    const int f0 = b * 16 + (tid & 3) * 4;  // float4 index within row k

    if (tid < Kc) sAs[tid] = g_asum[tid];
    __syncthreads();

    const float4* gv4 = (const float4*)g_V;
    const float4* c4  = (const float4*)c;
    float4* gvw = (float4*)g_V;
    const float ask = sAs[k];

    float4 v4[4];
#pragma unroll
    for (int r = 0; r < 4; r++) {
        float4 a = gv4[k * 64 + f0 + r];
        float4 cc = c4[k * 64 + f0 + r];
        v4[r].x = a.x - cc.x * ask;
        v4[r].y = a.y - cc.y * ask;
        v4[r].z = a.z - cc.z * ask;
        v4[r].w = a.w - cc.w * ask;
        gvw[k * 64 + f0 + r] = make_float4(0.f, 0.f, 0.f, 0.f);  // re-zero
        int dd = (tid & 3) * 16 + r * 4;
        *(float4*)&sV[k * 72 + dd] = v4[r];
    }
    __syncthreads();

    // column sumsq over k (64 threads, conflict-free: banks (d + 8k) distinct per k)
    if (tid < 64) {
        float ss = 0.0f;
#pragma unroll 8
        for (int kk2 = 0; kk2 < 64; kk2++) {
            float t = sV[kk2 * 72 + tid];
            ss += t * t;
        }
        sRinv[tid] = 1.0f / fmaxf(sqrtf(ss), 1e-12f);
    }
    __syncthreads();

    // scale, write g_Vn, accumulate row partial (this thread: one k, 16 d's)
    float4* vn4 = (float4*)g_Vn;
    float rp = 0.0f;
#pragma unroll
    for (int r = 0; r < 4; r++) {
        int dd = (tid & 3) * 16 + r * 4;
        float4 t = v4[r];
        t.x *= sRinv[dd + 0]; t.y *= sRinv[dd + 1];
        t.z *= sRinv[dd + 2]; t.w *= sRinv[dd + 3];
        rp += t.x * t.x + t.y * t.y + t.z * t.z + t.w * t.w;
        vn4[k * 64 + f0 + r] = t;
    }
    scr[tid] = rp;
    __syncthreads();
    if (tid < 64)
        g_rowp[b * 64 + tid] = scr[tid * 4] + scr[tid * 4 + 1] + scr[tid * 4 + 2] + scr[tid * 4 + 3];
}

// ------------------------- finalize, stage 2 (4 CTAs x 256) -------------------------
__global__ __launch_bounds__(256) void finalize2_kernel(float* __restrict__ out) {
    __shared__ float sRR[64];
    const int tid = threadIdx.x;
    const int b = blockIdx.x;
    if (tid < 64) {
        float rs = g_rowp[tid] + g_rowp[64 + tid] + g_rowp[128 + tid] + g_rowp[192 + tid];
        sRR[tid] = 1.0f / fmaxf(sqrtf(rs), 1e-12f);
        if (b == 0) g_asum[tid] = 0.0f;   // re-zero for next replay
    }
    __syncthreads();
    const int k = tid >> 2;
    const int f0 = b * 16 + (tid & 3) * 4;
    const float rr = sRR[k];
    const float4* vn4 = (const float4*)g_Vn;
    float4* o4 = (float4*)out;
#pragma unroll
    for (int r = 0; r < 4; r++) {
        float4 t = vn4[k * 64 + f0 + r];
        t.x *= rr; t.y *= rr; t.z *= rr; t.w *= rr;
        o4[k * 64 + f0 + r] = t;
    }
}

extern "C" void kernel_launch(void* const* d_in, const int* in_sizes, int n_in,
                              void* d_out, int out_size) {
    const float* x      = (const float*)d_in[0];
    const float* c      = (const float*)d_in[1];
    const float* conv_w = (const float*)d_in[2];
    const float* conv_b = (const float*)d_in[3];
    float* out = (float*)d_out;

    const int N = in_sizes[0] / Dc;
    const int numTiles = N / TN;

    int nsm = 148;
    cudaDeviceGetAttribute(&nsm, cudaDevAttrMultiProcessorCount, 0);

    cudaFuncSetAttribute(netvlad_tc_kernel,
                         cudaFuncAttributeMaxDynamicSharedMemorySize, SM_TOTAL);

    // g_V / g_asum are zero-initialized statics; finalize kernels re-zero
    // them after reading, so no separate zero pass is needed per replay.
    netvlad_tc_kernel<<<nsm, NTHREADS, SM_TOTAL>>>(x, conv_w, conv_b, N, numTiles);
    finalize1_kernel<<<4, 256>>>(c);
    finalize2_kernel<<<4, 256>>>(out);
}

// round 16
// speedup vs baseline: 1.1129x; 1.1129x over previous
#include <cuda_runtime.h>
#include <cuda_bf16.h>
#include <stdint.h>
#include <math.h>

#define Dc 256
#define Kc 64
#define TN 64
#define NTHREADS 384

#if defined(__CUDA_ARCH_FEAT_SM103_ALL) || defined(__CUDA_ARCH_FEAT_SM100_ALL)
#define TC_OK 1
#else
#define TC_OK 0
#endif

// ---- shared memory layout (bytes, from dynamic smem base) ----
#define SM_TMEMPTR 0
#define SM_MB1A    16          // mb1[0]@+16, mb1[1]@+24
#define SM_MB2A    32          // mb2[0]@+32, mb2[1]@+40
#define SM_B       64          // 64 floats bias (pre-scaled by log2e)
#define SM_SCRP    512         // 128 floats partial sums
#define SM_WH      2048        // W hi [128 k2][256 d] bf16 SW128 blocked (64KB)
#define SM_XDH0    (SM_WH   + 65536)   // X hi buf0 [256 d][64 n] (32KB)
#define SM_XDH1    (SM_XDH0 + 32768)
#define SM_AH0     (SM_XDH1 + 32768)   // a hi buf0 [64 k][64 n] (8KB)
#define SM_AH1     (SM_AH0  + 8192)
#define SM_TOTAL   (SM_AH1  + 8192)    // 149504 B

// idesc: kind::f16, dtype=F32, atype=btype=BF16, N=64, M=128
#define IDESC  ((1u<<4) | (1u<<7) | (1u<<10) | (8u<<17) | (8u<<24))
#define IDESC1 (IDESC | (1u<<16))       // + b_major (B is MN-major)

#define SWZ(o) ((o) ^ (((o) >> 3) & 0x70))

// SW128 descriptor: layout=2, version=1, SBO=64, LBO=1 (same for K/MN major;
// the b_major idesc bit carries the transpose).
#define DESC_BASE    0x4000404000010000ULL

#define LOG2E 1.4426950408889634f

__device__ float g_V[Kc * Dc];
__device__ float g_asum[Kc];
__device__ float g_Vn[Kc * Dc];   // column-normalized V (finalize scratch)
__device__ float g_rowp[4 * Kc];  // per-CTA row sumsq partials

// ------------------------- PTX helpers -------------------------
__device__ __forceinline__ uint32_t smem_u32(const void* p) {
    uint32_t a;
    asm("{ .reg .u64 t; cvta.to.shared.u64 t, %1; cvt.u32.u64 %0, t; }" : "=r"(a) : "l"(p));
    return a;
}
__device__ __forceinline__ uint64_t make_desc(uint32_t addr) {
    return DESC_BASE | ((uint64_t)(addr >> 4) & 0x3FFF);
}
#if TC_OK
__device__ __forceinline__ void mma_f16_ss(uint32_t d_tmem, uint64_t a_desc,
                                           uint64_t b_desc, uint32_t idesc, int acc) {
    asm volatile(
        "{\n\t.reg .pred p;\n\tsetp.ne.u32 p, %4, 0;\n\t"
        "tcgen05.mma.cta_group::1.kind::f16 [%0], %1, %2, %3, {%5, %5, %5, %5}, p;\n\t}"
        :: "r"(d_tmem), "l"(a_desc), "l"(b_desc), "r"(idesc), "r"((uint32_t)acc), "r"(0u)
        : "memory");
}
#endif
#define TC_COMMIT(mbar) \
    asm volatile("tcgen05.commit.cta_group::1.mbarrier::arrive::one.shared::cluster.b64 [%0];" \
                 :: "r"(mbar) : "memory")
#define TC_ALLOC(dst, n) \
    asm volatile("tcgen05.alloc.cta_group::1.sync.aligned.shared::cta.b32 [%0], %1;" \
                 :: "r"(dst), "r"(n) : "memory")
#define TC_RELINQ() asm volatile("tcgen05.relinquish_alloc_permit.cta_group::1.sync.aligned;")
#define TC_DEALLOC(base, n) \
    asm volatile("tcgen05.dealloc.cta_group::1.sync.aligned.b32 %0, %1;" :: "r"(base), "r"(n))
#define TC_WAIT_LD() asm volatile("tcgen05.wait::ld.sync.aligned;" ::: "memory")
#define TC_FENCE_AFTER() asm volatile("tcgen05.fence::after_thread_sync;" ::: "memory")
#define TC_FENCE_BEFORE() asm volatile("tcgen05.fence::before_thread_sync;" ::: "memory")
#define FENCE_ASYNC() asm volatile("fence.proxy.async.shared::cta;" ::: "memory")
#define MB_INIT(addr, cnt) \
    asm volatile("mbarrier.init.shared.b64 [%0], %1;" :: "r"(addr), "r"((uint32_t)(cnt)) : "memory")
#define MB_INVAL(addr) asm volatile("mbarrier.inval.shared.b64 [%0];" :: "r"(addr) : "memory")
#define BAR_SYNC(id, cnt) \
    asm volatile("bar.sync %0, %1;" :: "r"(id), "r"(cnt) : "memory")

#define MB_WAIT(mbar, ph) do {                                                  \
    uint32_t _m = (mbar); uint32_t _p = (uint32_t)(ph); uint32_t _done;         \
    asm volatile("{\n\t.reg .pred p;\n\t"                                       \
        "mbarrier.try_wait.parity.acquire.cta.shared::cta.b64 p, [%1], %2;\n\t" \
        "selp.b32 %0, 1, 0, p;\n\t}" : "=r"(_done) : "r"(_m), "r"(_p) : "memory"); \
    if (!_done) {                                                               \
        asm volatile("{\n\t.reg .pred P1;\n\t"                                  \
            "WL_%=:\n\t"                                                        \
            "mbarrier.try_wait.parity.acquire.cta.shared::cta.b64 P1, [%0], %1, 0x989680;\n\t" \
            "@P1 bra.uni WD_%=;\n\t"                                            \
            "bra.uni WL_%=;\n\t"                                                \
            "WD_%=:\n\t}" :: "r"(_m), "r"(_p) : "memory");                      \
    }                                                                           \
} while (0)

#define TC_LD_X32(r, addr)                                                      \
    asm volatile("tcgen05.ld.sync.aligned.32x32b.x32.b32 "                      \
        "{%0, %1, %2, %3, %4, %5, %6, %7, %8, %9, %10, %11, %12, %13, %14, %15, " \
        " %16, %17, %18, %19, %20, %21, %22, %23, %24, %25, %26, %27, %28, %29, %30, %31}, [%32];" \
        : "=r"((r)[0]),  "=r"((r)[1]),  "=r"((r)[2]),  "=r"((r)[3]),            \
          "=r"((r)[4]),  "=r"((r)[5]),  "=r"((r)[6]),  "=r"((r)[7]),            \
          "=r"((r)[8]),  "=r"((r)[9]),  "=r"((r)[10]), "=r"((r)[11]),           \
          "=r"((r)[12]), "=r"((r)[13]), "=r"((r)[14]), "=r"((r)[15]),           \
          "=r"((r)[16]), "=r"((r)[17]), "=r"((r)[18]), "=r"((r)[19]),           \
          "=r"((r)[20]), "=r"((r)[21]), "=r"((r)[22]), "=r"((r)[23]),           \
          "=r"((r)[24]), "=r"((r)[25]), "=r"((r)[26]), "=r"((r)[27]),           \
          "=r"((r)[28]), "=r"((r)[29]), "=r"((r)[30]), "=r"((r)[31])            \
        : "r"(addr))

__device__ __forceinline__ uint32_t b2u(__nv_bfloat162 v) {
    return *(uint32_t*)&v;
}

// ------------------------- main kernel -------------------------
__global__ __launch_bounds__(NTHREADS, 1) __cluster_dims__(1, 1, 1)
void netvlad_tc_kernel(const float* __restrict__ x,
                       const float* __restrict__ conv_w,
                       const float* __restrict__ conv_b,
                       int N, int numTiles) {
#if TC_OK
    extern __shared__ char smem[];
    const uint32_t sbase = smem_u32(smem);
    const int tid  = threadIdx.x;
    const int wid  = tid >> 5;
    const int lane = tid & 31;

    // init
    if (tid == 0) {
        MB_INIT(sbase + SM_MB1A + 0, 1); MB_INIT(sbase + SM_MB1A + 8, 1);
        MB_INIT(sbase + SM_MB2A + 0, 1); MB_INIT(sbase + SM_MB2A + 8, 1);
    }
    if (wid == 0) { TC_ALLOC(sbase + SM_TMEMPTR, 256); TC_RELINQ(); }
    if (tid < Kc) *(float*)(smem + SM_B + tid * 4) = conv_b[tid] * LOG2E;
    __syncthreads();
    uint32_t tmem;
    asm volatile("ld.shared.b32 %0, [%1];" : "=r"(tmem) : "r"(sbase + SM_TMEMPTR));

    // stage W hi (pre-scaled by log2e), M=128 (rows 64-127 duplicate rows 0-63).
    for (int i = tid; i < (Kc * Dc) / 4; i += NTHREADS) {
        int k = i >> 6;
        int d0 = (i & 63) * 4;
        float4 w4 = reinterpret_cast<const float4*>(conv_w)[i];
        __nv_bfloat162 h0 = __float22bfloat162_rn(make_float2(w4.x * LOG2E, w4.y * LOG2E));
        __nv_bfloat162 h1 = __float22bfloat162_rn(make_float2(w4.z * LOG2E, w4.w * LOG2E));
        uint32_t o = ((uint32_t)((k >> 3) + ((d0 >> 6) << 4)) << 10) + ((k & 7) << 7) + ((d0 & 63) << 1);
        o = SWZ(o);
        uint2 hv = make_uint2(b2u(h0), b2u(h1));
        *(uint2*)(smem + SM_WH + o) = hv;
        *(uint2*)(smem + SM_WH + o + 8192) = hv;
    }
    FENCE_ASYNC();
    __syncthreads();

    // descriptors
    const uint64_t dWh = make_desc(sbase + SM_WH);
    const uint64_t dX0 = make_desc(sbase + SM_XDH0);
    const uint64_t dX1 = make_desc(sbase + SM_XDH1);
    const uint64_t dA0 = make_desc(sbase + SM_AH0);
    const uint64_t dA1 = make_desc(sbase + SM_AH1);
    const float* sBf = (const float*)(smem + SM_B);
    float* scrP = (float*)(smem + SM_SCRP);

    float asum_local = 0.0f;
    int cnt = 0;
    int kk = 0;

    if (tid < 256) {
        // ================= PRODUCER (warps 0-7, 256 threads) =================
        uint32_t ph2 = 0;
        for (int tile = blockIdx.x; tile < numTiles; tile += gridDim.x, cnt++) {
            const int buf = cnt & 1;
            const int n0 = tile * TN;
            const int xb = buf ? SM_XDH1 : SM_XDH0;

            // 16 float4 per thread, all issued before the wait
            float4 v[16];
#pragma unroll
            for (int j = 0; j < 16; j++) {
                int i = tid + 256 * j;
                v[j] = *(reinterpret_cast<const float4*>(x + (size_t)(i >> 4) * N + n0) + (i & 15));
            }

            if (cnt >= 2) {
                MB_WAIT(sbase + SM_MB2A + 8 * buf, (ph2 >> buf) & 1);
                ph2 ^= (1u << buf);
            }

#pragma unroll
            for (int j = 0; j < 16; j++) {
                int i = tid + 256 * j;
                int d = i >> 4, n = (i & 15) * 4;
                __nv_bfloat162 h0 = __float22bfloat162_rn(make_float2(v[j].x, v[j].y));
                __nv_bfloat162 h1 = __float22bfloat162_rn(make_float2(v[j].z, v[j].w));
                uint32_t od = ((uint32_t)(d >> 3) << 10) + ((d & 7) << 7) + (n << 1);
                od = SWZ(od);
                *(uint2*)(smem + xb + od) = make_uint2(b2u(h0), b2u(h1));
            }
            FENCE_ASYNC();
            BAR_SYNC(1, 256);

            if (tid == 0) {
                const uint64_t bt = buf ? dX1 : dX0;
#pragma unroll
                for (int s = 0; s < 16; s++) {
                    uint64_t ao = (uint64_t)(((s >> 2) * 1024) + ((s & 3) * 2));
                    uint64_t bo = (uint64_t)(s * 128);
                    mma_f16_ss(tmem + buf * 64, dWh + ao, bt + bo, IDESC1, s != 0);
                }
                TC_COMMIT(sbase + SM_MB1A + 8 * buf);
            }
        }
    } else {
        // ================= CONSUMER (warps 8-11, 128 threads) =================
        const int cw = wid - 8;                 // 0..3
        kk = ((cw & 1) << 5) + lane;            // k index
        const int nh = cw >> 1;                 // n-half
        const float bk = sBf[kk];
        uint32_t ph1 = 0;

        for (int tile = blockIdx.x; tile < numTiles; tile += gridDim.x, cnt++) {
            const int buf = cnt & 1;
            const int ab = buf ? SM_AH1 : SM_AH0;

            MB_WAIT(sbase + SM_MB1A + 8 * buf, (ph1 >> buf) & 1);
            ph1 ^= (1u << buf);
            TC_FENCE_AFTER();
            uint32_t au[32];
            TC_LD_X32(au, tmem + buf * 64 + nh * 32);
            TC_WAIT_LD();
            TC_FENCE_BEFORE();

            float er[32], sr[32];
#pragma unroll
            for (int j = 0; j < 32; j++) {
                er[j] = exp2f(__uint_as_float(au[j]) + bk);
                sr[j] = er[j];
            }
            // fold-reduce: lane l ends with sum over 32 k-lanes for n = nh*32+l
#pragma unroll
            for (int off = 16; off > 0; off >>= 1) {
#pragma unroll
                for (int j = 0; j < 16; j++) {
                    if (j < off) {
                        float x0 = sr[j], x1 = sr[off + j];
                        float mine = (lane & off) ? x1 : x0;
                        float send = (lane & off) ? x0 : x1;
                        float theirs = __shfl_xor_sync(0xffffffffu, send, off);
                        sr[j] = mine + theirs;
                    }
                }
            }
            scrP[cw * 32 + lane] = sr[0];
            BAR_SYNC(2, 128);
            // lane l holds rinv for column n = nh*32 + l
            const float rinv_l = 1.0f / (sr[0] + scrP[(cw ^ 1) * 32 + lane]);

            float as = 0.0f;
#pragma unroll
            for (int q = 0; q < 4; q++) {
                uint32_t hv[4];
#pragma unroll
                for (int r = 0; r < 4; r++) {
                    int j = q * 8 + r * 2;
                    float a0 = er[j] * __shfl_sync(0xffffffffu, rinv_l, j);
                    float a1 = er[j + 1] * __shfl_sync(0xffffffffu, rinv_l, j + 1);
                    __nv_bfloat162 h2 = __float22bfloat162_rn(make_float2(a0, a1));
                    float2 f2 = __bfloat1622float2(h2);
                    as += f2.x + f2.y;   // asum from ROUNDED a (matches GEMM2 operand)
                    hv[r] = b2u(h2);
                }
                uint32_t o = ((uint32_t)(kk >> 3) << 10) + ((kk & 7) << 7) + ((uint32_t)(nh * 32 + q * 8) << 1);
                o = SWZ(o);
                *(uint4*)(smem + ab + o) = make_uint4(hv[0], hv[1], hv[2], hv[3]);
            }
            asum_local += as;
            FENCE_ASYNC();
            BAR_SYNC(2, 128);

            if (tid == 256) {
                const uint64_t dXp = buf ? dX1 : dX0;
                const uint64_t dAp = buf ? dA1 : dA0;
#pragma unroll
                for (int h = 0; h < 2; h++)
#pragma unroll
                    for (int s = 0; s < 4; s++) {
                        int acc = !(cnt == 0 && s == 0);
                        mma_f16_ss(tmem + 128 + 64 * h,
                                   dXp + (uint64_t)(h * 1024 + s * 2),
                                   dAp + (uint64_t)(s * 2), IDESC, acc);
                    }
                TC_COMMIT(sbase + SM_MB2A + 8 * buf);
            }
        }
    }

    __syncthreads();

    // ---- final: wait outstanding GEMM2 per buffer, then flush ----
    if (cnt >= 1) {
        int C0 = (cnt + 1) >> 1;
        int C1 = cnt >> 1;
        if (C0 >= 1) MB_WAIT(sbase + SM_MB2A + 0, (uint32_t)((C0 - 1) & 1));
        if (C1 >= 1) MB_WAIT(sbase + SM_MB2A + 8, (uint32_t)((C1 - 1) & 1));
        TC_FENCE_AFTER();
        if (tid < 256) {
            uint32_t r[64];
            uint32_t cbase = tmem + 128 + ((tid >= 128) ? 64 : 0);
            TC_LD_X32(r, cbase);
            TC_LD_X32(r + 32, cbase + 32);
            TC_WAIT_LD();
#pragma unroll
            for (int c = 0; c < 64; c++)
                atomicAdd(&g_V[c * Dc + tid], __uint_as_float(r[c]));
        } else {
            atomicAdd(&g_asum[kk], asum_local);
        }
    }
    __syncthreads();
    if (tid == 0) {
        MB_INVAL(sbase + SM_MB1A + 0); MB_INVAL(sbase + SM_MB1A + 8);
        MB_INVAL(sbase + SM_MB2A + 0); MB_INVAL(sbase + SM_MB2A + 8);
    }
    __syncthreads();
    if (wid == 0) TC_DEALLOC(tmem, 256);
#else
    // ---------- FFMA fallback (correct on non-a targets; never the fast path) ----------
    extern __shared__ float fsm[];
    float* sW  = fsm;                  // [64][257]
    float* sXT = sW + Kc * 257;        // [64][257]
    float* sA  = sXT + TN * 257;       // [64][65]
    float* sB  = sA + Kc * 65;         // [64]
    const int tid = threadIdx.x;
    for (int i = tid; i < (Kc * Dc) / 4; i += NTHREADS) {
        int k = (i * 4) / Dc, d = (i * 4) % Dc;
        float4 w4 = reinterpret_cast<const float4*>(conv_w)[i];
        float* p = &sW[k * 257 + d];
        p[0] = w4.x; p[1] = w4.y; p[2] = w4.z; p[3] = w4.w;
    }
    if (tid < Kc) sB[tid] = conv_b[tid];
    __syncthreads();
    const int tid2 = tid & 255;
    const int tn = tid2 & 15, tk = tid2 >> 4;
    const int td = tid2 & 31, tk2 = tid2 >> 5;
    float vacc[8][8];
#pragma unroll
    for (int i = 0; i < 8; i++)
#pragma unroll
        for (int j = 0; j < 8; j++) vacc[i][j] = 0.0f;
    float asum_acc = 0.0f;
    for (int tile = blockIdx.x; tile < numTiles; tile += gridDim.x) {
        const int n0 = tile * TN;
        __syncthreads();
        for (int i = tid; i < (Dc * TN) / 4; i += NTHREADS) {
            int d = i >> 4, ng = i & 15;
            float4 v = reinterpret_cast<const float4*>(x + (size_t)d * N + n0)[ng];
            int nb = ng * 4;
            sXT[(nb + 0) * 257 + d] = v.x; sXT[(nb + 1) * 257 + d] = v.y;
            sXT[(nb + 2) * 257 + d] = v.z; sXT[(nb + 3) * 257 + d] = v.w;
        }
        __syncthreads();
        if (tid < 256) {
            float acc[4][4];
#pragma unroll
            for (int i = 0; i < 4; i++)
#pragma unroll
                for (int j = 0; j < 4; j++) acc[i][j] = 0.0f;
#pragma unroll 4
            for (int d = 0; d < Dc; d++) {
                float wv[4], xv[4];
#pragma unroll
                for (int i = 0; i < 4; i++) wv[i] = sW[(tk * 4 + i) * 257 + d];
#pragma unroll
                for (int j = 0; j < 4; j++) xv[j] = sXT[(tn * 4 + j) * 257 + d];
#pragma unroll
                for (int i = 0; i < 4; i++)
#pragma unroll
                    for (int j = 0; j < 4; j++) acc[i][j] += wv[i] * xv[j];
            }
#pragma unroll
            for (int i = 0; i < 4; i++) {
                float b = sB[tk * 4 + i];
#pragma unroll
                for (int j = 0; j < 4; j++)
                    sA[(tk * 4 + i) * 65 + (tn * 4 + j)] = acc[i][j] + b;
            }
        }
        __syncthreads();
        if (tid < TN) {
            const int n = tid;
            float m = -1e30f;
            for (int k = 0; k < Kc; k++) m = fmaxf(m, sA[k * 65 + n]);
            float s = 0.0f;
            for (int k = 0; k < Kc; k++) {
                float e = __expf(sA[k * 65 + n] - m);
                sA[k * 65 + n] = e; s += e;
            }
            float r = 1.0f / s;
            for (int k = 0; k < Kc; k++) sA[k * 65 + n] *= r;
        }
        __syncthreads();
        if (tid < Kc) {
            float s = 0.0f;
            for (int n = 0; n < TN; n++) s += sA[tid * 65 + n];
            asum_acc += s;
        }
        if (tid < 256) {
#pragma unroll 2
            for (int n = 0; n < TN; n++) {
                float av[8], xv[8];
#pragma unroll
                for (int i = 0; i < 8; i++) av[i] = sA[(tk2 * 8 + i) * 65 + n];
#pragma unroll
                for (int j = 0; j < 8; j++) xv[j] = sXT[n * 257 + td + 32 * j];
#pragma unroll
                for (int i = 0; i < 8; i++)
#pragma unroll
                    for (int j = 0; j < 8; j++) vacc[i][j] += av[i] * xv[j];
            }
        }
    }
    if (tid < 256) {
#pragma unroll
        for (int i = 0; i < 8; i++)
#pragma unroll
            for (int j = 0; j < 8; j++)
                atomicAdd(&g_V[(tk2 * 8 + i) * Dc + td + 32 * j], vacc[i][j]);
    }
    if (tid < Kc) atomicAdd(&g_asum[tid], asum_acc);
#endif
}

// ------------------------- finalize, stage 1 (4 CTAs x 256) -------------------------
__global__ __launch_bounds__(256) void finalize1_kernel(const float* __restrict__ c) {
    __shared__ float sAs[64];
    __shared__ float sV[64 * 72];     // [k][dd], stride 72
    __shared__ float sRinv[64];
    __shared__ float scr[256];

    const int tid = threadIdx.x;
    const int b = blockIdx.x;
    const int k = tid >> 2;                 // 0..63
    const int f0 = b * 16 + (tid & 3) * 4;  // float4 index within row k

    if (tid < Kc) sAs[tid] = g_asum[tid];
    __syncthreads();

    const float4* gv4 = (const float4*)g_V;
    const float4* c4  = (const float4*)c;
    float4* gvw = (float4*)g_V;
    const float ask = sAs[k];

    float4 v4[4];
#pragma unroll
    for (int r = 0; r < 4; r++) {
        float4 a = gv4[k * 64 + f0 + r];
        float4 cc = c4[k * 64 + f0 + r];
        v4[r].x = a.x - cc.x * ask;
        v4[r].y = a.y - cc.y * ask;
        v4[r].z = a.z - cc.z * ask;
        v4[r].w = a.w - cc.w * ask;
        gvw[k * 64 + f0 + r] = make_float4(0.f, 0.f, 0.f, 0.f);  // re-zero
        int dd = (tid & 3) * 16 + r * 4;
        *(float4*)&sV[k * 72 + dd] = v4[r];
    }
    __syncthreads();

    if (tid < 64) {
        float ss = 0.0f;
#pragma unroll 8
        for (int kk2 = 0; kk2 < 64; kk2++) {
            float t = sV[kk2 * 72 + tid];
            ss += t * t;
        }
        sRinv[tid] = 1.0f / fmaxf(sqrtf(ss), 1e-12f);
    }
    __syncthreads();

    float4* vn4 = (float4*)g_Vn;
    float rp = 0.0f;
#pragma unroll
    for (int r = 0; r < 4; r++) {
        int dd = (tid & 3) * 16 + r * 4;
        float4 t = v4[r];
        t.x *= sRinv[dd + 0]; t.y *= sRinv[dd + 1];
        t.z *= sRinv[dd + 2]; t.w *= sRinv[dd + 3];
        rp += t.x * t.x + t.y * t.y + t.z * t.z + t.w * t.w;
        vn4[k * 64 + f0 + r] = t;
    }
    scr[tid] = rp;
    __syncthreads();
    if (tid < 64)
        g_rowp[b * 64 + tid] = scr[tid * 4] + scr[tid * 4 + 1] + scr[tid * 4 + 2] + scr[tid * 4 + 3];
}

// ------------------------- finalize, stage 2 (4 CTAs x 256) -------------------------
__global__ __launch_bounds__(256) void finalize2_kernel(float* __restrict__ out) {
    __shared__ float sRR[64];
    const int tid = threadIdx.x;
    const int b = blockIdx.x;
    if (tid < 64) {
        float rs = g_rowp[tid] + g_rowp[64 + tid] + g_rowp[128 + tid] + g_rowp[192 + tid];
        sRR[tid] = 1.0f / fmaxf(sqrtf(rs), 1e-12f);
        if (b == 0) g_asum[tid] = 0.0f;   // re-zero for next replay
    }
    __syncthreads();
    const int k = tid >> 2;
    const int f0 = b * 16 + (tid & 3) * 4;
    const float rr = sRR[k];
    const float4* vn4 = (const float4*)g_Vn;
    float4* o4 = (float4*)out;
#pragma unroll
    for (int r = 0; r < 4; r++) {
        float4 t = vn4[k * 64 + f0 + r];
        t.x *= rr; t.y *= rr; t.z *= rr; t.w *= rr;
        o4[k * 64 + f0 + r] = t;
    }
}

extern "C" void kernel_launch(void* const* d_in, const int* in_sizes, int n_in,
                              void* d_out, int out_size) {
    const float* x      = (const float*)d_in[0];
    const float* c      = (const float*)d_in[1];
    const float* conv_w = (const float*)d_in[2];
    const float* conv_b = (const float*)d_in[3];
    float* out = (float*)d_out;

    const int N = in_sizes[0] / Dc;
    const int numTiles = N / TN;

    int nsm = 148;
    cudaDeviceGetAttribute(&nsm, cudaDevAttrMultiProcessorCount, 0);

    cudaFuncSetAttribute(netvlad_tc_kernel,
                         cudaFuncAttributeMaxDynamicSharedMemorySize, SM_TOTAL);

    // g_V / g_asum are zero-initialized statics; finalize kernels re-zero
    // them after reading, so no separate zero pass is needed per replay.
    netvlad_tc_kernel<<<nsm, NTHREADS, SM_TOTAL>>>(x, conv_w, conv_b, N, numTiles);
    finalize1_kernel<<<4, 256>>>(c);
    finalize2_kernel<<<4, 256>>>(out);
}